// round 8
// baseline (speedup 1.0000x reference)
#include <cuda_runtime.h>
#include <cuda_fp16.h>

#define N_NODES 10000
#define D_IN    128
#define H1      128
#define H2      64
#define EMB     64
#define CAP     256      // fixed bucket capacity per destination node
#define NEG_SLOPE 0.2f
#define FULLMASK 0xffffffffu

// ---------------- scratch (device globals; no allocation allowed) -----------
__device__ __half g_h1h[N_NODES * H1];   // GEMM outputs stored fp16 (gather payload)
__device__ __half g_h2h[N_NODES * H2];
__device__ float  g_x1[N_NODES * H1];    // agg outputs stay fp32 (GEMM A operands)
__device__ float  g_x2[N_NODES * H2];
__device__ float  g_as[N_NODES];
__device__ float  g_ad[N_NODES];
__device__ int    g_cnt[N_NODES];
__device__ int    g_csr[N_NODES * CAP];  // bucket CSR: row i at i*CAP

__device__ __forceinline__ const float* abuf(int sel) {
    return (sel == 1) ? g_x1 : g_x2;
}

// ---------------- init -------------------------------------------------------
__global__ void zero_init_kernel() {
    int i = blockIdx.x * blockDim.x + threadIdx.x;
    if (i < N_NODES) {
        g_cnt[i] = 0;
        g_as[i] = 0.f;
        g_ad[i] = 0.f;
    }
}

// ---------------- single-pass bucket CSR fill --------------------------------
__global__ void fill_bucket_kernel(const int* __restrict__ ei, int E) {
    int t = blockIdx.x * blockDim.x + threadIdx.x;
    int e0 = t * 2;
    if (e0 >= E) return;
    if (e0 + 2 <= E && ((E & 1) == 0)) {
        int2 s2 = *(const int2*)&ei[e0];
        int2 d2 = *(const int2*)&ei[E + e0];
        int p0 = ((unsigned)d2.x < N_NODES) ? atomicAdd(&g_cnt[d2.x], 1) : CAP;
        int p1 = ((unsigned)d2.y < N_NODES) ? atomicAdd(&g_cnt[d2.y], 1) : CAP;
        if (p0 < CAP && (unsigned)s2.x < N_NODES) g_csr[d2.x * CAP + p0] = s2.x;
        if (p1 < CAP && (unsigned)s2.y < N_NODES) g_csr[d2.y * CAP + p1] = s2.y;
    } else {
        for (int e = e0; e < E && e < e0 + 2; e++) {
            int s = ei[e];
            int d = ei[E + e];
            if ((unsigned)s < N_NODES && (unsigned)d < N_NODES) {
                int pos = atomicAdd(&g_cnt[d], 1);
                if (pos < CAP) g_csr[d * CAP + pos] = s;
            }
        }
    }
}

// ---------------- fp32 tiled GEMM ---------------------------------------------
// C = A @ B (+bias). Output either fp32 (Cext) or fp16 scratch (h_sel: 0->g_h1h,
// 1->g_h2h). If a_src != nullptr, also computes per-row attention dots into
// g_as/g_ad (direct store when gridDim.x==1, else atomicAdd into pre-zeroed).
__global__ void gemm_kernel(const float* __restrict__ Aext, int a_sel,
                            const float* __restrict__ B,
                            const float* __restrict__ bias,
                            float* __restrict__ Cext, int h_sel,
                            int M, int Nn, int K,
                            const float* __restrict__ a_src,
                            const float* __restrict__ a_dst) {
    const float* A = Aext ? Aext : abuf(a_sel);

    __shared__ __align__(16) float As[8][64];
    __shared__ __align__(16) float Bs[8][64];
    const int tid  = threadIdx.x;             // 256 threads
    const int trow = tid >> 4;                // 0..15
    const int tcol = tid & 15;                // 0..15
    const int m0 = blockIdx.y * 64;
    const int n0 = blockIdx.x * 64;
    float acc[4][4] = {};

    for (int k0 = 0; k0 < K; k0 += 8) {
        for (int t = tid; t < 512; t += 256) {
            int r = t >> 3, c = t & 7;
            int gr = m0 + r;
            As[c][r] = (gr < M) ? A[gr * K + k0 + c] : 0.f;
        }
        for (int t = tid; t < 512; t += 256) {
            int r = t >> 6, c = t & 63;
            Bs[r][c] = B[(k0 + r) * Nn + n0 + c];
        }
        __syncthreads();
#pragma unroll
        for (int kk = 0; kk < 8; kk++) {
            float4 a4 = *(const float4*)&As[kk][trow * 4];
            float4 b4 = *(const float4*)&Bs[kk][tcol * 4];
            float a[4] = {a4.x, a4.y, a4.z, a4.w};
            float b[4] = {b4.x, b4.y, b4.z, b4.w};
#pragma unroll
            for (int i = 0; i < 4; i++)
#pragma unroll
                for (int j = 0; j < 4; j++)
                    acc[i][j] += a[i] * b[j];
        }
        __syncthreads();
    }

    if (Cext) {
#pragma unroll
        for (int i = 0; i < 4; i++) {
            int row = m0 + trow * 4 + i;
            if (row < M) {
#pragma unroll
                for (int j = 0; j < 4; j++) {
                    int col = n0 + tcol * 4 + j;
                    float v = acc[i][j];
                    if (bias) v += bias[col];
                    Cext[row * Nn + col] = v;
                }
            }
        }
    } else {
        __half* Ch = (h_sel == 0) ? g_h1h : g_h2h;
#pragma unroll
        for (int i = 0; i < 4; i++) {
            int row = m0 + trow * 4 + i;
            if (row < M) {
                int col = n0 + tcol * 4;
                __half2 p0 = __floats2half2_rn(acc[i][0], acc[i][1]);
                __half2 p1 = __floats2half2_rn(acc[i][2], acc[i][3]);
                uint2 u;
                u.x = *reinterpret_cast<unsigned*>(&p0);
                u.y = *reinterpret_cast<unsigned*>(&p1);
                *(uint2*)&Ch[row * Nn + col] = u;
            }
        }
    }

    // fused attention dots (from fp32 accumulators)
    if (a_src) {
        float asv[4], adv[4];
#pragma unroll
        for (int j = 0; j < 4; j++) {
            asv[j] = a_src[n0 + tcol * 4 + j];
            adv[j] = a_dst[n0 + tcol * 4 + j];
        }
        bool direct = (gridDim.x == 1);
#pragma unroll
        for (int i = 0; i < 4; i++) {
            float ds = 0.f, dd = 0.f;
#pragma unroll
            for (int j = 0; j < 4; j++) {
                ds += acc[i][j] * asv[j];
                dd += acc[i][j] * adv[j];
            }
#pragma unroll
            for (int off = 8; off; off >>= 1) {
                ds += __shfl_xor_sync(FULLMASK, ds, off);
                dd += __shfl_xor_sync(FULLMASK, dd, off);
            }
            int row = m0 + trow * 4 + i;
            if (tcol == 0 && row < M) {
                if (direct) {
                    g_as[row] = ds;
                    g_ad[row] = dd;
                } else {
                    atomicAdd(&g_as[row], ds);
                    atomicAdd(&g_ad[row], dd);
                }
            }
        }
    }
}

__device__ __forceinline__ float leaky(float x) {
    return x > 0.f ? x : NEG_SLOPE * x;
}

// ---------------- GAT aggregation: warp per destination node ----------------
// Lane-parallel fp32 weights (1 gather + 1 exp per lane per 32 edges), weights
// broadcast as packed half2; features accumulated with HFMA2 into fp16 partials
// flushed to fp32 accumulators every 8 edges (bounds fp16 accumulation error).
template <int H>
__global__ void __launch_bounds__(128) gat_agg_kernel(const float* __restrict__ bias) {
    const __half* hb = (H == 128) ? g_h1h : g_h2h;
    float* out       = (H == 128) ? g_x1 : g_x2;

    int i = (blockIdx.x * blockDim.x + threadIdx.x) >> 5;
    if (i >= N_NODES) return;
    int lane = threadIdx.x & 31;

    float adi = g_ad[i];
    int deg = g_cnt[i];
    if (deg > CAP) deg = CAP;
    const int* row = &g_csr[i * CAP];

    constexpr int V = H / 32;
    // self loop (fp32 path)
    float es = __expf(leaky(g_as[i] + adi));
    float zl = (lane == 0) ? es : 0.f;
    float acc[V];
    if (V == 4) {
        uint2 u = *(const uint2*)&hb[i * H + lane * 4];
        float2 f0 = __half22float2(*reinterpret_cast<const __half2*>(&u.x));
        float2 f1 = __half22float2(*reinterpret_cast<const __half2*>(&u.y));
        acc[0] = es * f0.x; acc[1] = es * f0.y;
        acc[2] = es * f1.x; acc[3] = es * f1.y;
    } else {
        float2 f = __half22float2(*(const __half2*)&hb[i * H + lane * 2]);
        acc[0] = es * f.x; acc[1] = es * f.y;
    }

    const __half2 h2zero = __float2half2_rn(0.f);

    for (int base = 0; base < deg; base += 32) {
        int rem = deg - base;
        if (rem > 32) rem = 32;

        // each lane: fp32 weight for its own edge; broadcast copy as half2
        int      idx = 0;
        unsigned wp  = 0;
        if (lane < rem) {
            idx = __ldg(&row[base + lane]);
            float e = __expf(leaky(__ldg(&g_as[idx]) + adi));
            zl += e;
            __half2 wh = __float2half2_rn(e);
            wp = *reinterpret_cast<unsigned*>(&wh);
        }

        int k = 0;
        // full 8-edge sub-chunks, unrolled: 8 gathers in flight, HFMA2 accumulate
        for (; k + 8 <= rem; k += 8) {
            __half2 p0 = h2zero, p1 = h2zero;
#pragma unroll
            for (int kk = 0; kk < 8; kk++) {
                int      s = __shfl_sync(FULLMASK, idx, k + kk);
                unsigned w = __shfl_sync(FULLMASK, wp, k + kk);
                __half2 wh = *reinterpret_cast<__half2*>(&w);
                if (V == 4) {
                    uint2 u = *(const uint2*)&hb[s * H + lane * 4];
                    p0 = __hfma2(*reinterpret_cast<__half2*>(&u.x), wh, p0);
                    p1 = __hfma2(*reinterpret_cast<__half2*>(&u.y), wh, p1);
                } else {
                    unsigned u = *(const unsigned*)&hb[s * H + lane * 2];
                    p0 = __hfma2(*reinterpret_cast<__half2*>(&u), wh, p0);
                }
            }
            float2 f0 = __half22float2(p0);
            acc[0] += f0.x; acc[1] += f0.y;
            if (V == 4) {
                float2 f1 = __half22float2(p1);
                acc[2] += f1.x; acc[3] += f1.y;
            }
        }
        // tail (< 8 edges)
        if (k < rem) {
            __half2 p0 = h2zero, p1 = h2zero;
            for (; k < rem; ++k) {
                int      s = __shfl_sync(FULLMASK, idx, k);
                unsigned w = __shfl_sync(FULLMASK, wp, k);
                __half2 wh = *reinterpret_cast<__half2*>(&w);
                if (V == 4) {
                    uint2 u = *(const uint2*)&hb[s * H + lane * 4];
                    p0 = __hfma2(*reinterpret_cast<__half2*>(&u.x), wh, p0);
                    p1 = __hfma2(*reinterpret_cast<__half2*>(&u.y), wh, p1);
                } else {
                    unsigned u = *(const unsigned*)&hb[s * H + lane * 2];
                    p0 = __hfma2(*reinterpret_cast<__half2*>(&u), wh, p0);
                }
            }
            float2 f0 = __half22float2(p0);
            acc[0] += f0.x; acc[1] += f0.y;
            if (V == 4) {
                float2 f1 = __half22float2(p1);
                acc[2] += f1.x; acc[3] += f1.y;
            }
        }
    }

#pragma unroll
    for (int off = 16; off; off >>= 1) zl += __shfl_xor_sync(FULLMASK, zl, off);

    float inv = 1.f / zl;
#pragma unroll
    for (int v = 0; v < V; v++) {
        float r = acc[v] * inv + bias[lane * V + v];
        out[i * H + lane * V + v] = r > 0.f ? r : 0.f;
    }
}

// ---------------- launch -----------------------------------------------------
extern "C" void kernel_launch(void* const* d_in, const int* in_sizes, int n_in,
                              void* d_out, int out_size) {
    const float* x    = (const float*)d_in[0];
    const int*   ei   = (const int*)d_in[1];       // int32 edge_index [2, E]
    const float* W1   = (const float*)d_in[2];
    const float* a_s1 = (const float*)d_in[3];
    const float* a_d1 = (const float*)d_in[4];
    const float* b1   = (const float*)d_in[5];
    const float* W2   = (const float*)d_in[6];
    const float* a_s2 = (const float*)d_in[7];
    const float* a_d2 = (const float*)d_in[8];
    const float* b2   = (const float*)d_in[9];
    const float* Wp   = (const float*)d_in[10];
    const float* bp   = (const float*)d_in[11];
    const int E = in_sizes[1] / 2;

    const int TB = 256;
    const int AB = 128;

    zero_init_kernel<<<(N_NODES + TB - 1) / TB, TB>>>();
    fill_bucket_kernel<<<(E + TB * 2 - 1) / (TB * 2), TB>>>(ei, E);

    const int aggBlocks = (N_NODES * 32 + AB - 1) / AB;

    // layer 1: h1(fp16) = x @ W1 (+fused dots) ; x1 = agg(h1)
    dim3 g1(H1 / 64, (N_NODES + 63) / 64);
    gemm_kernel<<<g1, TB>>>(x, -1, W1, nullptr, nullptr, 0, N_NODES, H1, D_IN,
                            a_s1, a_d1);
    gat_agg_kernel<H1><<<aggBlocks, AB>>>(b1);

    // layer 2: h2(fp16) = x1 @ W2 (+fused dots, direct store) ; x2 = agg(h2)
    dim3 g2(H2 / 64, (N_NODES + 63) / 64);
    gemm_kernel<<<g2, TB>>>(nullptr, 1, W2, nullptr, nullptr, 1, N_NODES, H2, H1,
                            a_s2, a_d2);
    gat_agg_kernel<H2><<<aggBlocks, AB>>>(b2);

    // projection: out = x2 @ Wp + bp (fp32)
    dim3 g3(EMB / 64, (N_NODES + 63) / 64);
    gemm_kernel<<<g3, TB>>>(nullptr, 2, Wp, bp, (float*)d_out, -1, N_NODES, EMB, H2,
                            nullptr, nullptr);
}

// round 9
// speedup vs baseline: 1.0669x; 1.0669x over previous
#include <cuda_runtime.h>
#include <cuda_fp16.h>

#define N_NODES 10000
#define D_IN    128
#define H1      128
#define H2      64
#define EMB     64
#define CAP     256      // fixed bucket capacity per destination node
#define NEG_SLOPE 0.2f
#define FULLMASK 0xffffffffu

// ---------------- scratch (device globals; no allocation allowed) -----------
__device__ __half g_h1h[N_NODES * H1];   // GEMM outputs stored fp16 (gather payload)
__device__ __half g_h2h[N_NODES * H2];
__device__ float  g_x1[N_NODES * H1];    // agg outputs stay fp32 (GEMM A operands)
__device__ float  g_x2[N_NODES * H2];
__device__ float  g_as[N_NODES];
__device__ float  g_ad[N_NODES];
__device__ int    g_cnt[N_NODES];
__device__ int    g_csr[N_NODES * CAP];  // bucket CSR: row i at i*CAP

__device__ __forceinline__ const float* abuf(int sel) {
    return (sel == 1) ? g_x1 : g_x2;
}

// ---------------- init -------------------------------------------------------
__global__ void zero_init_kernel() {
    int i = blockIdx.x * blockDim.x + threadIdx.x;
    if (i < N_NODES) {
        g_cnt[i] = 0;
        g_as[i] = 0.f;
        g_ad[i] = 0.f;
    }
}

// ---------------- single-pass bucket CSR fill --------------------------------
__global__ void fill_bucket_kernel(const int* __restrict__ ei, int E) {
    int t = blockIdx.x * blockDim.x + threadIdx.x;
    int e0 = t * 2;
    if (e0 >= E) return;
    if (e0 + 2 <= E && ((E & 1) == 0)) {
        int2 s2 = *(const int2*)&ei[e0];
        int2 d2 = *(const int2*)&ei[E + e0];
        int p0 = ((unsigned)d2.x < N_NODES) ? atomicAdd(&g_cnt[d2.x], 1) : CAP;
        int p1 = ((unsigned)d2.y < N_NODES) ? atomicAdd(&g_cnt[d2.y], 1) : CAP;
        if (p0 < CAP && (unsigned)s2.x < N_NODES) g_csr[d2.x * CAP + p0] = s2.x;
        if (p1 < CAP && (unsigned)s2.y < N_NODES) g_csr[d2.y * CAP + p1] = s2.y;
    } else {
        for (int e = e0; e < E && e < e0 + 2; e++) {
            int s = ei[e];
            int d = ei[E + e];
            if ((unsigned)s < N_NODES && (unsigned)d < N_NODES) {
                int pos = atomicAdd(&g_cnt[d], 1);
                if (pos < CAP) g_csr[d * CAP + pos] = s;
            }
        }
    }
}

// ---------------- fp32 tiled GEMM ---------------------------------------------
// C = A @ B (+bias). Output either fp32 (Cext) or fp16 scratch (h_sel: 0->g_h1h,
// 1->g_h2h). If a_src != nullptr, also computes per-row attention dots into
// g_as/g_ad (direct store when gridDim.x==1, else atomicAdd into pre-zeroed).
__global__ void gemm_kernel(const float* __restrict__ Aext, int a_sel,
                            const float* __restrict__ B,
                            const float* __restrict__ bias,
                            float* __restrict__ Cext, int h_sel,
                            int M, int Nn, int K,
                            const float* __restrict__ a_src,
                            const float* __restrict__ a_dst) {
    const float* A = Aext ? Aext : abuf(a_sel);

    __shared__ __align__(16) float As[8][64];
    __shared__ __align__(16) float Bs[8][64];
    const int tid  = threadIdx.x;             // 256 threads
    const int trow = tid >> 4;                // 0..15
    const int tcol = tid & 15;                // 0..15
    const int m0 = blockIdx.y * 64;
    const int n0 = blockIdx.x * 64;
    float acc[4][4] = {};

    for (int k0 = 0; k0 < K; k0 += 8) {
        for (int t = tid; t < 512; t += 256) {
            int r = t >> 3, c = t & 7;
            int gr = m0 + r;
            As[c][r] = (gr < M) ? A[gr * K + k0 + c] : 0.f;
        }
        for (int t = tid; t < 512; t += 256) {
            int r = t >> 6, c = t & 63;
            Bs[r][c] = B[(k0 + r) * Nn + n0 + c];
        }
        __syncthreads();
#pragma unroll
        for (int kk = 0; kk < 8; kk++) {
            float4 a4 = *(const float4*)&As[kk][trow * 4];
            float4 b4 = *(const float4*)&Bs[kk][tcol * 4];
            float a[4] = {a4.x, a4.y, a4.z, a4.w};
            float b[4] = {b4.x, b4.y, b4.z, b4.w};
#pragma unroll
            for (int i = 0; i < 4; i++)
#pragma unroll
                for (int j = 0; j < 4; j++)
                    acc[i][j] += a[i] * b[j];
        }
        __syncthreads();
    }

    if (Cext) {
#pragma unroll
        for (int i = 0; i < 4; i++) {
            int row = m0 + trow * 4 + i;
            if (row < M) {
#pragma unroll
                for (int j = 0; j < 4; j++) {
                    int col = n0 + tcol * 4 + j;
                    float v = acc[i][j];
                    if (bias) v += bias[col];
                    Cext[row * Nn + col] = v;
                }
            }
        }
    } else {
        __half* Ch = (h_sel == 0) ? g_h1h : g_h2h;
#pragma unroll
        for (int i = 0; i < 4; i++) {
            int row = m0 + trow * 4 + i;
            if (row < M) {
                int col = n0 + tcol * 4;
                __half2 p0 = __floats2half2_rn(acc[i][0], acc[i][1]);
                __half2 p1 = __floats2half2_rn(acc[i][2], acc[i][3]);
                uint2 u;
                u.x = *reinterpret_cast<unsigned*>(&p0);
                u.y = *reinterpret_cast<unsigned*>(&p1);
                *(uint2*)&Ch[row * Nn + col] = u;
            }
        }
    }

    // fused attention dots (from fp32 accumulators)
    if (a_src) {
        float asv[4], adv[4];
#pragma unroll
        for (int j = 0; j < 4; j++) {
            asv[j] = a_src[n0 + tcol * 4 + j];
            adv[j] = a_dst[n0 + tcol * 4 + j];
        }
        bool direct = (gridDim.x == 1);
#pragma unroll
        for (int i = 0; i < 4; i++) {
            float ds = 0.f, dd = 0.f;
#pragma unroll
            for (int j = 0; j < 4; j++) {
                ds += acc[i][j] * asv[j];
                dd += acc[i][j] * adv[j];
            }
#pragma unroll
            for (int off = 8; off; off >>= 1) {
                ds += __shfl_xor_sync(FULLMASK, ds, off);
                dd += __shfl_xor_sync(FULLMASK, dd, off);
            }
            int row = m0 + trow * 4 + i;
            if (tcol == 0 && row < M) {
                if (direct) {
                    g_as[row] = ds;
                    g_ad[row] = dd;
                } else {
                    atomicAdd(&g_as[row], ds);
                    atomicAdd(&g_ad[row], dd);
                }
            }
        }
    }
}

__device__ __forceinline__ float leaky(float x) {
    return x > 0.f ? x : NEG_SLOPE * x;
}

// ---------------- GAT aggregation: warp per destination node ----------------
// Lane-parallel fp32 weights; HFMA2 accumulation into TWO alternating partial
// sets (independent chains, restores gather MLP) flushed to fp32 every 8 edges.
template <int H>
__global__ void __launch_bounds__(128) gat_agg_kernel(const float* __restrict__ bias) {
    const __half* hb = (H == 128) ? g_h1h : g_h2h;
    float* out       = (H == 128) ? g_x1 : g_x2;

    int i = (blockIdx.x * blockDim.x + threadIdx.x) >> 5;
    if (i >= N_NODES) return;
    int lane = threadIdx.x & 31;

    float adi = g_ad[i];
    int deg = g_cnt[i];
    if (deg > CAP) deg = CAP;
    const int* row = &g_csr[i * CAP];

    constexpr int V = H / 32;
    // self loop (fp32 path)
    float es = __expf(leaky(g_as[i] + adi));
    float zl = (lane == 0) ? es : 0.f;
    float acc[V];
    if (V == 4) {
        uint2 u = *(const uint2*)&hb[i * H + lane * 4];
        float2 f0 = __half22float2(*reinterpret_cast<const __half2*>(&u.x));
        float2 f1 = __half22float2(*reinterpret_cast<const __half2*>(&u.y));
        acc[0] = es * f0.x; acc[1] = es * f0.y;
        acc[2] = es * f1.x; acc[3] = es * f1.y;
    } else {
        float2 f = __half22float2(*(const __half2*)&hb[i * H + lane * 2]);
        acc[0] = es * f.x; acc[1] = es * f.y;
    }

    const __half2 h2zero = __float2half2_rn(0.f);

    for (int base = 0; base < deg; base += 32) {
        int rem = deg - base;
        if (rem > 32) rem = 32;

        // each lane: fp32 weight for its own edge; broadcast copy as half2
        int      idx = 0;
        unsigned wp  = 0;
        if (lane < rem) {
            idx = __ldg(&row[base + lane]);
            float e = __expf(leaky(__ldg(&g_as[idx]) + adi));
            zl += e;
            __half2 wh = __float2half2_rn(e);
            wp = *reinterpret_cast<unsigned*>(&wh);
        }

        int k = 0;
        // 8-edge chunks: even/odd alternating partials -> 2 independent chains
        for (; k + 8 <= rem; k += 8) {
            __half2 pA0 = h2zero, pA1 = h2zero;   // even slots
            __half2 pB0 = h2zero, pB1 = h2zero;   // odd slots
#pragma unroll
            for (int kk = 0; kk < 8; kk += 2) {
                int      sa = __shfl_sync(FULLMASK, idx, k + kk);
                unsigned wa = __shfl_sync(FULLMASK, wp, k + kk);
                int      sb = __shfl_sync(FULLMASK, idx, k + kk + 1);
                unsigned wb = __shfl_sync(FULLMASK, wp, k + kk + 1);
                __half2 wha = *reinterpret_cast<__half2*>(&wa);
                __half2 whb = *reinterpret_cast<__half2*>(&wb);
                if (V == 4) {
                    uint2 ua = *(const uint2*)&hb[sa * H + lane * 4];
                    uint2 ub = *(const uint2*)&hb[sb * H + lane * 4];
                    pA0 = __hfma2(*reinterpret_cast<__half2*>(&ua.x), wha, pA0);
                    pA1 = __hfma2(*reinterpret_cast<__half2*>(&ua.y), wha, pA1);
                    pB0 = __hfma2(*reinterpret_cast<__half2*>(&ub.x), whb, pB0);
                    pB1 = __hfma2(*reinterpret_cast<__half2*>(&ub.y), whb, pB1);
                } else {
                    unsigned ua = *(const unsigned*)&hb[sa * H + lane * 2];
                    unsigned ub = *(const unsigned*)&hb[sb * H + lane * 2];
                    pA0 = __hfma2(*reinterpret_cast<__half2*>(&ua), wha, pA0);
                    pB0 = __hfma2(*reinterpret_cast<__half2*>(&ub), whb, pB0);
                }
            }
            float2 f0 = __half22float2(__hadd2(pA0, pB0));
            acc[0] += f0.x; acc[1] += f0.y;
            if (V == 4) {
                float2 f1 = __half22float2(__hadd2(pA1, pB1));
                acc[2] += f1.x; acc[3] += f1.y;
            }
        }
        // tail (< 8 edges): fp32 accumulation, avoids extra partial handling
        for (; k < rem; ++k) {
            int      s = __shfl_sync(FULLMASK, idx, k);
            unsigned w = __shfl_sync(FULLMASK, wp, k);
            __half2 wh = *reinterpret_cast<__half2*>(&w);
            float wf = __half2float(__low2half(wh));
            if (V == 4) {
                uint2 u = *(const uint2*)&hb[s * H + lane * 4];
                float2 a0 = __half22float2(*reinterpret_cast<__half2*>(&u.x));
                float2 b0 = __half22float2(*reinterpret_cast<__half2*>(&u.y));
                acc[0] += wf * a0.x; acc[1] += wf * a0.y;
                acc[2] += wf * b0.x; acc[3] += wf * b0.y;
            } else {
                unsigned u = *(const unsigned*)&hb[s * H + lane * 2];
                float2 f0 = __half22float2(*reinterpret_cast<__half2*>(&u));
                acc[0] += wf * f0.x; acc[1] += wf * f0.y;
            }
        }
    }

#pragma unroll
    for (int off = 16; off; off >>= 1) zl += __shfl_xor_sync(FULLMASK, zl, off);

    float inv = 1.f / zl;
#pragma unroll
    for (int v = 0; v < V; v++) {
        float r = acc[v] * inv + bias[lane * V + v];
        out[i * H + lane * V + v] = r > 0.f ? r : 0.f;
    }
}

// ---------------- launch -----------------------------------------------------
extern "C" void kernel_launch(void* const* d_in, const int* in_sizes, int n_in,
                              void* d_out, int out_size) {
    const float* x    = (const float*)d_in[0];
    const int*   ei   = (const int*)d_in[1];       // int32 edge_index [2, E]
    const float* W1   = (const float*)d_in[2];
    const float* a_s1 = (const float*)d_in[3];
    const float* a_d1 = (const float*)d_in[4];
    const float* b1   = (const float*)d_in[5];
    const float* W2   = (const float*)d_in[6];
    const float* a_s2 = (const float*)d_in[7];
    const float* a_d2 = (const float*)d_in[8];
    const float* b2   = (const float*)d_in[9];
    const float* Wp   = (const float*)d_in[10];
    const float* bp   = (const float*)d_in[11];
    const int E = in_sizes[1] / 2;

    const int TB = 256;
    const int AB = 128;

    zero_init_kernel<<<(N_NODES + TB - 1) / TB, TB>>>();
    fill_bucket_kernel<<<(E + TB * 2 - 1) / (TB * 2), TB>>>(ei, E);

    const int aggBlocks = (N_NODES * 32 + AB - 1) / AB;

    // layer 1: h1(fp16) = x @ W1 (+fused dots) ; x1 = agg(h1)
    dim3 g1(H1 / 64, (N_NODES + 63) / 64);
    gemm_kernel<<<g1, TB>>>(x, -1, W1, nullptr, nullptr, 0, N_NODES, H1, D_IN,
                            a_s1, a_d1);
    gat_agg_kernel<H1><<<aggBlocks, AB>>>(b1);

    // layer 2: h2(fp16) = x1 @ W2 (+fused dots, direct store) ; x2 = agg(h2)
    dim3 g2(H2 / 64, (N_NODES + 63) / 64);
    gemm_kernel<<<g2, TB>>>(nullptr, 1, W2, nullptr, nullptr, 1, N_NODES, H2, H1,
                            a_s2, a_d2);
    gat_agg_kernel<H2><<<aggBlocks, AB>>>(b2);

    // projection: out = x2 @ Wp + bp (fp32)
    dim3 g3(EMB / 64, (N_NODES + 63) / 64);
    gemm_kernel<<<g3, TB>>>(nullptr, 2, Wp, bp, (float*)d_out, -1, N_NODES, EMB, H2,
                            nullptr, nullptr);
}